// round 15
// baseline (speedup 1.0000x reference)
#include <cuda_runtime.h>
#include <math.h>
#include <stdint.h>

#define BSZ 8
#define SEQ 2048
#define DIM 1024
#define HID 4096
#define ROWS (BSZ*SEQ)

// ---------------- static device scratch ----------------
static __device__ float g_h  [(size_t)ROWS*DIM];
static __device__ float g_q  [(size_t)ROWS*DIM];
static __device__ float g_k  [(size_t)ROWS*DIM];
static __device__ float g_v  [(size_t)ROWS*DIM];
static __device__ float g_vt [(size_t)ROWS*DIM];           // per-batch [DIM,SEQ]
static __device__ float g_s  [(size_t)BSZ*SEQ*SEQ];
static __device__ float g_av [(size_t)ROWS*DIM];
static __device__ float g_x2 [(size_t)ROWS*DIM];
static __device__ float g_h2 [(size_t)ROWS*DIM];
static __device__ float g_f  [(size_t)ROWS*HID];
static __device__ float g_wqT[(size_t)DIM*DIM];            // [N,K] transposed+rounded
static __device__ float g_wkT[(size_t)DIM*DIM];
static __device__ float g_wvT[(size_t)DIM*DIM];
static __device__ float g_woT[(size_t)DIM*DIM];
static __device__ float g_w1T[(size_t)HID*DIM];
static __device__ float g_w2T[(size_t)DIM*HID];

// ---------------- helpers ----------------
__device__ __forceinline__ uint32_t smem_u32(const void* p) {
    uint32_t a;
    asm("{ .reg .u64 t; cvta.to.shared.u64 t, %1; cvt.u32.u64 %0, t; }" : "=r"(a) : "l"(p));
    return a;
}
__device__ __forceinline__ float rtf32(float v) {
    uint32_t u;
    asm("cvt.rna.tf32.f32 %0, %1;" : "=r"(u) : "f"(v));
    return __uint_as_float(u);
}
__device__ __forceinline__ void cp16(uint32_t dst, const void* src) {
    asm volatile("cp.async.cg.shared.global [%0], [%1], 16;" :: "r"(dst), "l"(src));
}
#define CP_COMMIT() asm volatile("cp.async.commit_group;")
#define CP_WAIT3()  asm volatile("cp.async.wait_group 3;")

#define MMA_TF32(d, a, b) \
    asm volatile("mma.sync.aligned.m16n8k8.row.col.f32.tf32.tf32.f32 " \
        "{%0,%1,%2,%3}, {%4,%5,%6,%7}, {%8,%9}, {%0,%1,%2,%3};" \
        : "+f"((d)[0]), "+f"((d)[1]), "+f"((d)[2]), "+f"((d)[3]) \
        : "r"((a)[0]), "r"((a)[1]), "r"((a)[2]), "r"((a)[3]), \
          "r"((b)[0]), "r"((b)[1]))

#define LDSM4(R0, R1, R2, R3, ADDR) \
    asm volatile("ldmatrix.sync.aligned.m8n8.x4.shared.b16 {%0,%1,%2,%3}, [%4];" \
        : "=r"(R0), "=r"(R1), "=r"(R2), "=r"(R3) : "r"(ADDR))

// ---------------- transpose + tf32-round: in [R,C] -> out [C,R] ----------------
__global__ void wt_kernel(const float* __restrict__ in, float* __restrict__ out,
                          int R, int C, long long sIn, long long sOut)
{
    __shared__ float t[32][33];
    const int tx = threadIdx.x, ty = threadIdx.y;
    const size_t zi = (size_t)blockIdx.z * sIn;
    const size_t zo = (size_t)blockIdx.z * sOut;
    const int c = blockIdx.x * 32 + tx;
#pragma unroll
    for (int k = 0; k < 4; ++k) {
        const int r = blockIdx.y * 32 + ty + k * 8;
        t[ty + k * 8][tx] = in[zi + (size_t)r * C + c];
    }
    __syncthreads();
    const int ocol = blockIdx.y * 32 + tx;
#pragma unroll
    for (int k = 0; k < 4; ++k) {
        const int orow = blockIdx.x * 32 + ty + k * 8;
        out[zo + (size_t)orow * R + ocol] = rtf32(t[tx][ty + k * 8]);
    }
}

// ---------------- LayerNorm (tf32-rounded output) ----------------
__global__ __launch_bounds__(256) void ln_kernel(
    const float* __restrict__ x, const float* __restrict__ g,
    const float* __restrict__ b, float* __restrict__ out)
{
    __shared__ float r0[256], r1[256];
    const int tid = threadIdx.x;
    const size_t row = blockIdx.x;
    const float4 v = reinterpret_cast<const float4*>(x + row * DIM)[tid];
    r0[tid] = v.x + v.y + v.z + v.w;
    r1[tid] = v.x*v.x + v.y*v.y + v.z*v.z + v.w*v.w;
    __syncthreads();
    for (int off = 128; off > 0; off >>= 1) {
        if (tid < off) { r0[tid] += r0[tid+off]; r1[tid] += r1[tid+off]; }
        __syncthreads();
    }
    const float mu  = r0[0] * (1.0f/DIM);
    const float inv = rsqrtf(r1[0] * (1.0f/DIM) - mu*mu + 1e-5f);
    const float4 gg = reinterpret_cast<const float4*>(g)[tid];
    const float4 bb = reinterpret_cast<const float4*>(b)[tid];
    float4 o;
    o.x = rtf32((v.x-mu)*inv*gg.x + bb.x);
    o.y = rtf32((v.y-mu)*inv*gg.y + bb.y);
    o.z = rtf32((v.z-mu)*inv*gg.z + bb.z);
    o.w = rtf32((v.w-mu)*inv*gg.w + bb.w);
    reinterpret_cast<float4*>(out + row * DIM)[tid] = o;
}

// ---------------- softmax (tf32-rounded probs) ----------------
__global__ __launch_bounds__(256) void softmax_kernel(float* __restrict__ sm)
{
    __shared__ float red[256];
    const int tid = threadIdx.x;
    float4* p4 = reinterpret_cast<float4*>(sm + (size_t)blockIdx.x * SEQ);
    float4 v0 = p4[tid], v1 = p4[tid + 256];
    float m = fmaxf(fmaxf(fmaxf(v0.x,v0.y), fmaxf(v0.z,v0.w)),
                    fmaxf(fmaxf(v1.x,v1.y), fmaxf(v1.z,v1.w)));
    red[tid] = m; __syncthreads();
    for (int off = 128; off > 0; off >>= 1) {
        if (tid < off) red[tid] = fmaxf(red[tid], red[tid+off]);
        __syncthreads();
    }
    m = red[0]; __syncthreads();
    v0.x = __expf(v0.x-m); v0.y = __expf(v0.y-m);
    v0.z = __expf(v0.z-m); v0.w = __expf(v0.w-m);
    v1.x = __expf(v1.x-m); v1.y = __expf(v1.y-m);
    v1.z = __expf(v1.z-m); v1.w = __expf(v1.w-m);
    red[tid] = v0.x+v0.y+v0.z+v0.w+v1.x+v1.y+v1.z+v1.w;
    __syncthreads();
    for (int off = 128; off > 0; off >>= 1) {
        if (tid < off) red[tid] += red[tid+off];
        __syncthreads();
    }
    const float inv = 1.0f / red[0];
    v0.x = rtf32(v0.x*inv); v0.y = rtf32(v0.y*inv);
    v0.z = rtf32(v0.z*inv); v0.w = rtf32(v0.w*inv);
    v1.x = rtf32(v1.x*inv); v1.y = rtf32(v1.y*inv);
    v1.z = rtf32(v1.z*inv); v1.w = rtf32(v1.w*inv);
    p4[tid] = v0;
    p4[tid + 256] = v1;
}

// ---------------- TF32 tensor-core GEMM (trans-B, ldmatrix, 128x256 tile) ----
// C[M,N] = epi(alpha * A[M,K] @ B[N,K]^T). A row-major lda, B n-major ldb.
// CTA tile 128x256x16, 8 warps (2x4), warp tile 64x64, occupancy 1.
// 5-stage cp.async pipeline, one __syncthreads per K-step.
// stage: A 128 rows x 20 floats (10240 B) + B 256 rows x 20 floats (20480 B).
#define STAGE_BYTES 30720
#define NSTAGE 5
#define SMEM_GEMM (NSTAGE * STAGE_BYTES)   /* 153600 B */

__device__ __forceinline__ void stage_load(
    uint32_t sbase, int slot, const float* Abase, const float* Bbase,
    int lda, int ldb, int k0, int tid)
{
    const uint32_t sA = sbase + slot * STAGE_BYTES;
    const uint32_t sB = sA + 10240;
#pragma unroll
    for (int h = 0; h < 2; ++h) {
        const int v = tid + h * 256;
        const int row = v >> 2, kv = v & 3;
        cp16(sA + (uint32_t)(row * 80 + kv * 16),
             Abase + (size_t)row * lda + k0 + kv * 4);
    }
#pragma unroll
    for (int h = 0; h < 4; ++h) {
        const int v = tid + h * 256;
        const int row = v >> 2, kv = v & 3;
        cp16(sB + (uint32_t)(row * 80 + kv * 16),
             Bbase + (size_t)row * ldb + k0 + kv * 4);
    }
}

template <bool GELU, bool ROUND>
__global__ __launch_bounds__(256, 1) void tf32_gemm(
    const float* __restrict__ A, const float* __restrict__ B,
    float* __restrict__ C, int K, int lda, int ldb, int ldc,
    long long sAa, long long sBb, long long sCc,
    float alpha, const float* __restrict__ bias,
    const float* __restrict__ res)
{
    extern __shared__ float smf[];
    const uint32_t sbase = smem_u32(smf);
    const int tid = threadIdx.x;
    const int lane = tid & 31, wid = tid >> 5;
    const int warpM = wid >> 2, warpN = wid & 3;      // 2 x 4 warps
    const int lr = lane >> 2, lc = lane & 3;

    const size_t rowBase = (size_t)blockIdx.y * 128;
    const size_t colBase = (size_t)blockIdx.x * 256;
    const float* Abase = A + (size_t)blockIdx.z * sAa + rowBase * lda;
    const float* Bbase = B + (size_t)blockIdx.z * sBb + colBase * ldb;

    // per-thread ldmatrix base offsets (bytes) within a stage
    const uint32_t aOff = (uint32_t)(((warpM*64 + (lane & 15)) * 20 +
                                     ((lane >> 4) & 1) * 4) * 4);
    const uint32_t bOff = 10240u + (uint32_t)(((warpN*64 + (lane & 7) +
                                     ((lane >> 4) & 1) * 8) * 20 +
                                     ((lane >> 3) & 1) * 4) * 4);

    float acc[4][8][4];
#pragma unroll
    for (int i = 0; i < 4; ++i)
#pragma unroll
        for (int j = 0; j < 8; ++j)
#pragma unroll
            for (int r = 0; r < 4; ++r) acc[i][j][r] = 0.0f;

    const int KT = K >> 4;
    stage_load(sbase, 0, Abase, Bbase, lda, ldb, 0,  tid); CP_COMMIT();
    stage_load(sbase, 1, Abase, Bbase, lda, ldb, 16, tid); CP_COMMIT();
    stage_load(sbase, 2, Abase, Bbase, lda, ldb, 32, tid); CP_COMMIT();
    stage_load(sbase, 3, Abase, Bbase, lda, ldb, 48, tid); CP_COMMIT();

    int slot = 0, wslot = 4;
    for (int t = 0; t < KT; ++t) {
        CP_WAIT3();
        __syncthreads();
        if (t + 4 < KT)
            stage_load(sbase, wslot, Abase, Bbase, lda, ldb, (t + 4) * 16, tid);
        CP_COMMIT();
        if (++wslot == NSTAGE) wslot = 0;

        const uint32_t sb0 = sbase + (uint32_t)slot * STAGE_BYTES;
        if (++slot == NSTAGE) slot = 0;
#pragma unroll
        for (int kk = 0; kk < 2; ++kk) {
            uint32_t af[4][4], bf[8][2];
#pragma unroll
            for (int i = 0; i < 4; ++i)
                LDSM4(af[i][0], af[i][1], af[i][2], af[i][3],
                      sb0 + aOff + (uint32_t)((i * 16 * 20 + kk * 8) * 4));
#pragma unroll
            for (int jp = 0; jp < 4; ++jp)
                LDSM4(bf[2*jp][0], bf[2*jp][1], bf[2*jp+1][0], bf[2*jp+1][1],
                      sb0 + bOff + (uint32_t)((jp * 16 * 20 + kk * 8) * 4));
#pragma unroll
            for (int i = 0; i < 4; ++i)
#pragma unroll
                for (int j = 0; j < 8; ++j)
                    MMA_TF32(acc[i][j], af[i], bf[j]);
        }
    }

    // ---- epilogue ----
    const size_t zC = (size_t)blockIdx.z * sCc;
#pragma unroll
    for (int i = 0; i < 4; ++i) {
        const size_t r0 = rowBase + warpM*64 + i*16 + lr;
#pragma unroll
        for (int half = 0; half < 2; ++half) {
            const size_t r = r0 + half*8;
#pragma unroll
            for (int j = 0; j < 8; ++j) {
                const size_t c = colBase + warpN*64 + j*8 + 2*lc;
                float v0 = acc[i][j][half*2 + 0] * alpha;
                float v1 = acc[i][j][half*2 + 1] * alpha;
                if (bias) { v0 += bias[c]; v1 += bias[c+1]; }
                if (res) {
                    const float2 rv = *reinterpret_cast<const float2*>(res + r*ldc + c);
                    v0 += rv.x; v1 += rv.y;
                }
                if (GELU) {
                    v0 = 0.5f * v0 * (1.0f + erff(v0 * 0.70710678118654752f));
                    v1 = 0.5f * v1 * (1.0f + erff(v1 * 0.70710678118654752f));
                }
                if (ROUND) { v0 = rtf32(v0); v1 = rtf32(v1); }
                float2 ov = {v0, v1};
                *reinterpret_cast<float2*>(C + zC + r*ldc + c) = ov;
            }
        }
    }
}

// ---------------- launch ----------------
extern "C" void kernel_launch(void* const* d_in, const int* in_sizes, int n_in,
                              void* d_out, int out_size)
{
    const float* x     = (const float*)d_in[0];
    const float* ln1_g = (const float*)d_in[1];
    const float* ln1_b = (const float*)d_in[2];
    const float* wq    = (const float*)d_in[3];
    const float* wk    = (const float*)d_in[4];
    const float* wv    = (const float*)d_in[5];
    const float* wo    = (const float*)d_in[6];
    const float* ln2_g = (const float*)d_in[7];
    const float* ln2_b = (const float*)d_in[8];
    const float* w1    = (const float*)d_in[9];
    const float* b1    = (const float*)d_in[10];
    const float* w2    = (const float*)d_in[11];
    const float* b2    = (const float*)d_in[12];
    float* out = (float*)d_out;

    void* p;
#define SYM(dst, s) cudaGetSymbolAddress(&p, s); float* dst = (float*)p
    SYM(ph,  g_h);   SYM(pq,  g_q);   SYM(pk,  g_k);   SYM(pv,  g_v);
    SYM(pvt, g_vt);  SYM(ps,  g_s);   SYM(pav, g_av);  SYM(px2, g_x2);
    SYM(ph2, g_h2);  SYM(pf,  g_f);
    SYM(pwqT, g_wqT); SYM(pwkT, g_wkT); SYM(pwvT, g_wvT); SYM(pwoT, g_woT);
    SYM(pw1T, g_w1T); SYM(pw2T, g_w2T);
#undef SYM

    cudaFuncSetAttribute(tf32_gemm<false,true>,
        cudaFuncAttributeMaxDynamicSharedMemorySize, SMEM_GEMM);
    cudaFuncSetAttribute(tf32_gemm<false,false>,
        cudaFuncAttributeMaxDynamicSharedMemorySize, SMEM_GEMM);
    cudaFuncSetAttribute(tf32_gemm<true,true>,
        cudaFuncAttributeMaxDynamicSharedMemorySize, SMEM_GEMM);

    const dim3 tb32(32, 8);
    // weight transposes+rounding: [K,N] -> [N,K]
    wt_kernel<<<dim3(32, 32, 1), tb32>>>(wq, pwqT, DIM, DIM, 0, 0);
    wt_kernel<<<dim3(32, 32, 1), tb32>>>(wk, pwkT, DIM, DIM, 0, 0);
    wt_kernel<<<dim3(32, 32, 1), tb32>>>(wv, pwvT, DIM, DIM, 0, 0);
    wt_kernel<<<dim3(32, 32, 1), tb32>>>(wo, pwoT, DIM, DIM, 0, 0);
    wt_kernel<<<dim3(128, 32, 1), tb32>>>(w1, pw1T, DIM, HID, 0, 0);
    wt_kernel<<<dim3(32, 128, 1), tb32>>>(w2, pw2T, HID, DIM, 0, 0);

    // h = ln1(x)
    ln_kernel<<<ROWS, 256>>>(x, ln1_g, ln1_b, ph);

    // q, k, v = h @ {wq, wk, wv}
    {
        dim3 g(DIM/256, ROWS/128, 1);
        tf32_gemm<false,true><<<g, 256, SMEM_GEMM>>>(
            ph, pwqT, pq, DIM, DIM, DIM, DIM, 0, 0, 0, 1.0f, nullptr, nullptr);
        tf32_gemm<false,true><<<g, 256, SMEM_GEMM>>>(
            ph, pwkT, pk, DIM, DIM, DIM, DIM, 0, 0, 0, 1.0f, nullptr, nullptr);
        tf32_gemm<false,true><<<g, 256, SMEM_GEMM>>>(
            ph, pwvT, pv, DIM, DIM, DIM, DIM, 0, 0, 0, 1.0f, nullptr, nullptr);
    }
    // vt = v^T per batch: [SEQ,DIM] -> [DIM,SEQ]
    wt_kernel<<<dim3(DIM/32, SEQ/32, BSZ), tb32>>>(pv, pvt, SEQ, DIM,
        (long long)SEQ*DIM, (long long)DIM*SEQ);
    // s = (q @ k^T) * 1/32
    tf32_gemm<false,false><<<dim3(SEQ/256, SEQ/128, BSZ), 256, SMEM_GEMM>>>(
        pq, pk, ps, DIM, DIM, DIM, SEQ,
        (long long)SEQ*DIM, (long long)SEQ*DIM, (long long)SEQ*SEQ,
        0.03125f, nullptr, nullptr);
    // softmax rows (in place, rounded probs)
    softmax_kernel<<<BSZ*SEQ, 256>>>(ps);
    // av = a @ v  (B = vt, n-major)
    tf32_gemm<false,true><<<dim3(DIM/256, SEQ/128, BSZ), 256, SMEM_GEMM>>>(
        ps, pvt, pav, SEQ, SEQ, SEQ, DIM,
        (long long)SEQ*SEQ, (long long)DIM*SEQ, (long long)SEQ*DIM,
        1.0f, nullptr, nullptr);
    // x2 = h + av @ wo
    tf32_gemm<false,false><<<dim3(DIM/256, ROWS/128, 1), 256, SMEM_GEMM>>>(
        pav, pwoT, px2, DIM, DIM, DIM, DIM, 0, 0, 0, 1.0f, nullptr, ph);
    // h2 = ln2(x2)
    ln_kernel<<<ROWS, 256>>>(px2, ln2_g, ln2_b, ph2);
    // f = gelu(h2 @ w1 + b1)
    tf32_gemm<true,true><<<dim3(HID/256, ROWS/128, 1), 256, SMEM_GEMM>>>(
        ph2, pw1T, pf, DIM, DIM, DIM, HID, 0, 0, 0, 1.0f, b1, nullptr);
    // out = x2 + f @ w2 + b2
    tf32_gemm<false,false><<<dim3(DIM/256, ROWS/128, 1), 256, SMEM_GEMM>>>(
        pf, pw2T, out, HID, HID, HID, DIM, 0, 0, 0, 1.0f, b2, px2);
}

// round 16
// speedup vs baseline: 1.3072x; 1.3072x over previous
#include <cuda_runtime.h>
#include <math.h>
#include <stdint.h>

#define BSZ 8
#define SEQ 2048
#define DIM 1024
#define HID 4096
#define ROWS (BSZ*SEQ)

// ---------------- static device scratch ----------------
static __device__ float g_h  [(size_t)ROWS*DIM];
static __device__ float g_q  [(size_t)ROWS*DIM];
static __device__ float g_k  [(size_t)ROWS*DIM];
static __device__ float g_v  [(size_t)ROWS*DIM];
static __device__ float g_vt [(size_t)ROWS*DIM];           // per-batch [DIM,SEQ]
static __device__ float g_s  [(size_t)BSZ*SEQ*SEQ];
static __device__ float g_av [(size_t)ROWS*DIM];
static __device__ float g_x2 [(size_t)ROWS*DIM];
static __device__ float g_h2 [(size_t)ROWS*DIM];
static __device__ float g_f  [(size_t)ROWS*HID];
static __device__ float g_wqT[(size_t)DIM*DIM];            // [N,K] transposed+rounded
static __device__ float g_wkT[(size_t)DIM*DIM];
static __device__ float g_wvT[(size_t)DIM*DIM];
static __device__ float g_woT[(size_t)DIM*DIM];
static __device__ float g_w1T[(size_t)HID*DIM];
static __device__ float g_w2T[(size_t)DIM*HID];

// ---------------- helpers ----------------
__device__ __forceinline__ uint32_t smem_u32(const void* p) {
    uint32_t a;
    asm("{ .reg .u64 t; cvta.to.shared.u64 t, %1; cvt.u32.u64 %0, t; }" : "=r"(a) : "l"(p));
    return a;
}
__device__ __forceinline__ float rtf32(float v) {
    uint32_t u;
    asm("cvt.rna.tf32.f32 %0, %1;" : "=r"(u) : "f"(v));
    return __uint_as_float(u);
}
__device__ __forceinline__ void cp16(uint32_t dst, const void* src) {
    asm volatile("cp.async.cg.shared.global [%0], [%1], 16;" :: "r"(dst), "l"(src));
}
#define CP_COMMIT() asm volatile("cp.async.commit_group;")
#define CP_WAIT1()  asm volatile("cp.async.wait_group 1;")

#define MMA_TF32(d, a, b) \
    asm volatile("mma.sync.aligned.m16n8k8.row.col.f32.tf32.tf32.f32 " \
        "{%0,%1,%2,%3}, {%4,%5,%6,%7}, {%8,%9}, {%0,%1,%2,%3};" \
        : "+f"((d)[0]), "+f"((d)[1]), "+f"((d)[2]), "+f"((d)[3]) \
        : "r"((a)[0]), "r"((a)[1]), "r"((a)[2]), "r"((a)[3]), \
          "r"((b)[0]), "r"((b)[1]))

#define LDSM4(R0, R1, R2, R3, ADDR) \
    asm volatile("ldmatrix.sync.aligned.m8n8.x4.shared.b16 {%0,%1,%2,%3}, [%4];" \
        : "=r"(R0), "=r"(R1), "=r"(R2), "=r"(R3) : "r"(ADDR))

// ---------------- transpose + tf32-round: in [R,C] -> out [C,R] ----------------
__global__ void wt_kernel(const float* __restrict__ in, float* __restrict__ out,
                          int R, int C, long long sIn, long long sOut)
{
    __shared__ float t[32][33];
    const int tx = threadIdx.x, ty = threadIdx.y;
    const size_t zi = (size_t)blockIdx.z * sIn;
    const size_t zo = (size_t)blockIdx.z * sOut;
    const int c = blockIdx.x * 32 + tx;
#pragma unroll
    for (int k = 0; k < 4; ++k) {
        const int r = blockIdx.y * 32 + ty + k * 8;
        t[ty + k * 8][tx] = in[zi + (size_t)r * C + c];
    }
    __syncthreads();
    const int ocol = blockIdx.y * 32 + tx;
#pragma unroll
    for (int k = 0; k < 4; ++k) {
        const int orow = blockIdx.x * 32 + ty + k * 8;
        out[zo + (size_t)orow * R + ocol] = rtf32(t[tx][ty + k * 8]);
    }
}

// ---------------- LayerNorm (tf32-rounded output) ----------------
__global__ __launch_bounds__(256) void ln_kernel(
    const float* __restrict__ x, const float* __restrict__ g,
    const float* __restrict__ b, float* __restrict__ out)
{
    __shared__ float r0[256], r1[256];
    const int tid = threadIdx.x;
    const size_t row = blockIdx.x;
    const float4 v = reinterpret_cast<const float4*>(x + row * DIM)[tid];
    r0[tid] = v.x + v.y + v.z + v.w;
    r1[tid] = v.x*v.x + v.y*v.y + v.z*v.z + v.w*v.w;
    __syncthreads();
    for (int off = 128; off > 0; off >>= 1) {
        if (tid < off) { r0[tid] += r0[tid+off]; r1[tid] += r1[tid+off]; }
        __syncthreads();
    }
    const float mu  = r0[0] * (1.0f/DIM);
    const float inv = rsqrtf(r1[0] * (1.0f/DIM) - mu*mu + 1e-5f);
    const float4 gg = reinterpret_cast<const float4*>(g)[tid];
    const float4 bb = reinterpret_cast<const float4*>(b)[tid];
    float4 o;
    o.x = rtf32((v.x-mu)*inv*gg.x + bb.x);
    o.y = rtf32((v.y-mu)*inv*gg.y + bb.y);
    o.z = rtf32((v.z-mu)*inv*gg.z + bb.z);
    o.w = rtf32((v.w-mu)*inv*gg.w + bb.w);
    reinterpret_cast<float4*>(out + row * DIM)[tid] = o;
}

// ---------------- softmax (tf32-rounded probs) ----------------
__global__ __launch_bounds__(256) void softmax_kernel(float* __restrict__ sm)
{
    __shared__ float red[256];
    const int tid = threadIdx.x;
    float4* p4 = reinterpret_cast<float4*>(sm + (size_t)blockIdx.x * SEQ);
    float4 v0 = p4[tid], v1 = p4[tid + 256];
    float m = fmaxf(fmaxf(fmaxf(v0.x,v0.y), fmaxf(v0.z,v0.w)),
                    fmaxf(fmaxf(v1.x,v1.y), fmaxf(v1.z,v1.w)));
    red[tid] = m; __syncthreads();
    for (int off = 128; off > 0; off >>= 1) {
        if (tid < off) red[tid] = fmaxf(red[tid], red[tid+off]);
        __syncthreads();
    }
    m = red[0]; __syncthreads();
    v0.x = __expf(v0.x-m); v0.y = __expf(v0.y-m);
    v0.z = __expf(v0.z-m); v0.w = __expf(v0.w-m);
    v1.x = __expf(v1.x-m); v1.y = __expf(v1.y-m);
    v1.z = __expf(v1.z-m); v1.w = __expf(v1.w-m);
    red[tid] = v0.x+v0.y+v0.z+v0.w+v1.x+v1.y+v1.z+v1.w;
    __syncthreads();
    for (int off = 128; off > 0; off >>= 1) {
        if (tid < off) red[tid] += red[tid+off];
        __syncthreads();
    }
    const float inv = 1.0f / red[0];
    v0.x = rtf32(v0.x*inv); v0.y = rtf32(v0.y*inv);
    v0.z = rtf32(v0.z*inv); v0.w = rtf32(v0.w*inv);
    v1.x = rtf32(v1.x*inv); v1.y = rtf32(v1.y*inv);
    v1.z = rtf32(v1.z*inv); v1.w = rtf32(v1.w*inv);
    p4[tid] = v0;
    p4[tid + 256] = v1;
}

// ---------------- TF32 tensor-core GEMM (trans-B, ldmatrix, K-chunk 32) ------
// C[M,N] = epi(alpha * A[M,K] @ B[N,K]^T). A row-major lda, B n-major ldb.
// CTA tile 128x128x32, 8 warps (2x4, warp tile 64x32), occupancy 2.
// 3-stage cp.async pipeline, ONE __syncthreads per 32-K chunk.
// stage: A 128 rows x 36 floats (18432 B) + B 128 rows x 36 floats = 36864 B.
#define STAGE_BYTES 36864
#define NSTAGE 3
#define SMEM_GEMM (NSTAGE * STAGE_BYTES)   /* 110592 B */

__device__ __forceinline__ void stage_load(
    uint32_t sbase, int slot, const float* Abase, const float* Bbase,
    int lda, int ldb, int k0, int tid)
{
    const uint32_t sA = sbase + slot * STAGE_BYTES;
    const uint32_t sB = sA + 18432;
#pragma unroll
    for (int h = 0; h < 4; ++h) {
        const int v = tid + h * 256;
        const int row = v >> 3, kv = v & 7;
        cp16(sA + (uint32_t)(row * 144 + kv * 16),
             Abase + (size_t)row * lda + k0 + kv * 4);
    }
#pragma unroll
    for (int h = 0; h < 4; ++h) {
        const int v = tid + h * 256;
        const int row = v >> 3, kv = v & 7;
        cp16(sB + (uint32_t)(row * 144 + kv * 16),
             Bbase + (size_t)row * ldb + k0 + kv * 4);
    }
}

template <bool GELU, bool ROUND>
__global__ __launch_bounds__(256, 2) void tf32_gemm(
    const float* __restrict__ A, const float* __restrict__ B,
    float* __restrict__ C, int K, int lda, int ldb, int ldc,
    long long sAa, long long sBb, long long sCc,
    float alpha, const float* __restrict__ bias,
    const float* __restrict__ res)
{
    extern __shared__ float smf[];
    const uint32_t sbase = smem_u32(smf);
    const int tid = threadIdx.x;
    const int lane = tid & 31, wid = tid >> 5;
    const int warpM = wid >> 2, warpN = wid & 3;
    const int lr = lane >> 2, lc = lane & 3;

    const size_t rowBase = (size_t)blockIdx.y * 128;
    const size_t colBase = (size_t)blockIdx.x * 128;
    const float* Abase = A + (size_t)blockIdx.z * sAa + rowBase * lda;
    const float* Bbase = B + (size_t)blockIdx.z * sBb + colBase * ldb;

    // per-thread ldmatrix base offsets (bytes) within a stage; row stride 144 B
    const uint32_t aOff = (uint32_t)(((warpM*64 + (lane & 15)) * 36 +
                                     ((lane >> 4) & 1) * 4) * 4);
    const uint32_t bOff = 18432u + (uint32_t)(((warpN*32 + (lane & 7) +
                                     ((lane >> 4) & 1) * 8) * 36 +
                                     ((lane >> 3) & 1) * 4) * 4);

    float acc[4][4][4];
#pragma unroll
    for (int i = 0; i < 4; ++i)
#pragma unroll
        for (int j = 0; j < 4; ++j)
#pragma unroll
            for (int r = 0; r < 4; ++r) acc[i][j][r] = 0.0f;

    const int KT = K >> 5;          // 32-K chunks
    stage_load(sbase, 0, Abase, Bbase, lda, ldb, 0,  tid); CP_COMMIT();
    stage_load(sbase, 1, Abase, Bbase, lda, ldb, 32, tid); CP_COMMIT();

    int slot = 0, wslot = 2;
    for (int t = 0; t < KT; ++t) {
        CP_WAIT1();          // chunk t landed (<=1 younger group pending)
        __syncthreads();     // visible to all; all warps done with slot being refilled
        if (t + 2 < KT)
            stage_load(sbase, wslot, Abase, Bbase, lda, ldb, (t + 2) * 32, tid);
        CP_COMMIT();
        if (++wslot == NSTAGE) wslot = 0;

        const uint32_t sb0 = sbase + (uint32_t)slot * STAGE_BYTES;
        if (++slot == NSTAGE) slot = 0;
#pragma unroll
        for (int kk = 0; kk < 4; ++kk) {
            uint32_t af[4][4], bf[4][2];
#pragma unroll
            for (int i = 0; i < 4; ++i)
                LDSM4(af[i][0], af[i][1], af[i][2], af[i][3],
                      sb0 + aOff + (uint32_t)((i * 16 * 36 + kk * 8) * 4));
#pragma unroll
            for (int jp = 0; jp < 2; ++jp)
                LDSM4(bf[2*jp][0], bf[2*jp][1], bf[2*jp+1][0], bf[2*jp+1][1],
                      sb0 + bOff + (uint32_t)((jp * 16 * 36 + kk * 8) * 4));
#pragma unroll
            for (int i = 0; i < 4; ++i)
#pragma unroll
                for (int j = 0; j < 4; ++j)
                    MMA_TF32(acc[i][j], af[i], bf[j]);
        }
    }

    // ---- epilogue ----
    const size_t zC = (size_t)blockIdx.z * sCc;
#pragma unroll
    for (int i = 0; i < 4; ++i) {
        const size_t r0 = rowBase + warpM*64 + i*16 + lr;
#pragma unroll
        for (int half = 0; half < 2; ++half) {
            const size_t r = r0 + half*8;
#pragma unroll
            for (int j = 0; j < 4; ++j) {
                const size_t c = colBase + warpN*32 + j*8 + 2*lc;
                float v0 = acc[i][j][half*2 + 0] * alpha;
                float v1 = acc[i][j][half*2 + 1] * alpha;
                if (bias) { v0 += bias[c]; v1 += bias[c+1]; }
                if (res) {
                    const float2 rv = *reinterpret_cast<const float2*>(res + r*ldc + c);
                    v0 += rv.x; v1 += rv.y;
                }
                if (GELU) {
                    v0 = 0.5f * v0 * (1.0f + erff(v0 * 0.70710678118654752f));
                    v1 = 0.5f * v1 * (1.0f + erff(v1 * 0.70710678118654752f));
                }
                if (ROUND) { v0 = rtf32(v0); v1 = rtf32(v1); }
                float2 ov = {v0, v1};
                *reinterpret_cast<float2*>(C + zC + r*ldc + c) = ov;
            }
        }
    }
}

// ---------------- launch ----------------
extern "C" void kernel_launch(void* const* d_in, const int* in_sizes, int n_in,
                              void* d_out, int out_size)
{
    const float* x     = (const float*)d_in[0];
    const float* ln1_g = (const float*)d_in[1];
    const float* ln1_b = (const float*)d_in[2];
    const float* wq    = (const float*)d_in[3];
    const float* wk    = (const float*)d_in[4];
    const float* wv    = (const float*)d_in[5];
    const float* wo    = (const float*)d_in[6];
    const float* ln2_g = (const float*)d_in[7];
    const float* ln2_b = (const float*)d_in[8];
    const float* w1    = (const float*)d_in[9];
    const float* b1    = (const float*)d_in[10];
    const float* w2    = (const float*)d_in[11];
    const float* b2    = (const float*)d_in[12];
    float* out = (float*)d_out;

    void* p;
#define SYM(dst, s) cudaGetSymbolAddress(&p, s); float* dst = (float*)p
    SYM(ph,  g_h);   SYM(pq,  g_q);   SYM(pk,  g_k);   SYM(pv,  g_v);
    SYM(pvt, g_vt);  SYM(ps,  g_s);   SYM(pav, g_av);  SYM(px2, g_x2);
    SYM(ph2, g_h2);  SYM(pf,  g_f);
    SYM(pwqT, g_wqT); SYM(pwkT, g_wkT); SYM(pwvT, g_wvT); SYM(pwoT, g_woT);
    SYM(pw1T, g_w1T); SYM(pw2T, g_w2T);
#undef SYM

    cudaFuncSetAttribute(tf32_gemm<false,true>,
        cudaFuncAttributeMaxDynamicSharedMemorySize, SMEM_GEMM);
    cudaFuncSetAttribute(tf32_gemm<false,false>,
        cudaFuncAttributeMaxDynamicSharedMemorySize, SMEM_GEMM);
    cudaFuncSetAttribute(tf32_gemm<true,true>,
        cudaFuncAttributeMaxDynamicSharedMemorySize, SMEM_GEMM);

    const dim3 tb32(32, 8);
    // weight transposes+rounding: [K,N] -> [N,K]
    wt_kernel<<<dim3(32, 32, 1), tb32>>>(wq, pwqT, DIM, DIM, 0, 0);
    wt_kernel<<<dim3(32, 32, 1), tb32>>>(wk, pwkT, DIM, DIM, 0, 0);
    wt_kernel<<<dim3(32, 32, 1), tb32>>>(wv, pwvT, DIM, DIM, 0, 0);
    wt_kernel<<<dim3(32, 32, 1), tb32>>>(wo, pwoT, DIM, DIM, 0, 0);
    wt_kernel<<<dim3(128, 32, 1), tb32>>>(w1, pw1T, DIM, HID, 0, 0);
    wt_kernel<<<dim3(32, 128, 1), tb32>>>(w2, pw2T, HID, DIM, 0, 0);

    // h = ln1(x)
    ln_kernel<<<ROWS, 256>>>(x, ln1_g, ln1_b, ph);

    // q, k, v = h @ {wq, wk, wv}
    {
        dim3 g(DIM/128, ROWS/128, 1);
        tf32_gemm<false,true><<<g, 256, SMEM_GEMM>>>(
            ph, pwqT, pq, DIM, DIM, DIM, DIM, 0, 0, 0, 1.0f, nullptr, nullptr);
        tf32_gemm<false,true><<<g, 256, SMEM_GEMM>>>(
            ph, pwkT, pk, DIM, DIM, DIM, DIM, 0, 0, 0, 1.0f, nullptr, nullptr);
        tf32_gemm<false,true><<<g, 256, SMEM_GEMM>>>(
            ph, pwvT, pv, DIM, DIM, DIM, DIM, 0, 0, 0, 1.0f, nullptr, nullptr);
    }
    // vt = v^T per batch: [SEQ,DIM] -> [DIM,SEQ]
    wt_kernel<<<dim3(DIM/32, SEQ/32, BSZ), tb32>>>(pv, pvt, SEQ, DIM,
        (long long)SEQ*DIM, (long long)DIM*SEQ);
    // s = (q @ k^T) * 1/32
    tf32_gemm<false,false><<<dim3(SEQ/128, SEQ/128, BSZ), 256, SMEM_GEMM>>>(
        pq, pk, ps, DIM, DIM, DIM, SEQ,
        (long long)SEQ*DIM, (long long)SEQ*DIM, (long long)SEQ*SEQ,
        0.03125f, nullptr, nullptr);
    // softmax rows (in place, rounded probs)
    softmax_kernel<<<BSZ*SEQ, 256>>>(ps);
    // av = a @ v  (B = vt, n-major)
    tf32_gemm<false,true><<<dim3(DIM/128, SEQ/128, BSZ), 256, SMEM_GEMM>>>(
        ps, pvt, pav, SEQ, SEQ, SEQ, DIM,
        (long long)SEQ*SEQ, (long long)DIM*SEQ, (long long)SEQ*DIM,
        1.0f, nullptr, nullptr);
    // x2 = h + av @ wo
    tf32_gemm<false,false><<<dim3(DIM/128, ROWS/128, 1), 256, SMEM_GEMM>>>(
        pav, pwoT, px2, DIM, DIM, DIM, DIM, 0, 0, 0, 1.0f, nullptr, ph);
    // h2 = ln2(x2)
    ln_kernel<<<ROWS, 256>>>(px2, ln2_g, ln2_b, ph2);
    // f = gelu(h2 @ w1 + b1)
    tf32_gemm<true,true><<<dim3(HID/128, ROWS/128, 1), 256, SMEM_GEMM>>>(
        ph2, pw1T, pf, DIM, DIM, DIM, HID, 0, 0, 0, 1.0f, b1, nullptr);
    // out = x2 + f @ w2 + b2
    tf32_gemm<false,false><<<dim3(DIM/128, ROWS/128, 1), 256, SMEM_GEMM>>>(
        pf, pw2T, out, HID, HID, HID, DIM, 0, 0, 0, 1.0f, b2, px2);
}